// round 1
// baseline (speedup 1.0000x reference)
#include <cuda_runtime.h>
#include <cstdint>

#define LOG2E 1.4426950408889634f

// Scratch for projected Q (normalized, /8 folded), K (normalized), V
__device__ float g_Q[8 * 2048 * 64];
__device__ float g_K[8 * 2048 * 64];
__device__ float g_V[8 * 2048 * 64];

__device__ __forceinline__ uint32_t f2tf(float x) {
    uint32_t y;
    asm("cvt.rna.tf32.f32 %0, %1;" : "=r"(y) : "f"(x));
    return y;
}

__device__ __forceinline__ void mma_tf32(float d[4], const uint32_t a[4],
                                         const uint32_t b[2], const float c[4]) {
    asm volatile(
        "mma.sync.aligned.m16n8k8.row.col.f32.tf32.tf32.f32 "
        "{%0,%1,%2,%3}, {%4,%5,%6,%7}, {%8,%9}, {%10,%11,%12,%13};"
        : "=f"(d[0]), "=f"(d[1]), "=f"(d[2]), "=f"(d[3])
        : "r"(a[0]), "r"(a[1]), "r"(a[2]), "r"(a[3]),
          "r"(b[0]), "r"(b[1]),
          "f"(c[0]), "f"(c[1]), "f"(c[2]), "f"(c[3]));
}

// ---------------------------------------------------------------------------
// Projection: out[16384,64] = X[16384,768] @ W[768,64] + bias, optional row
// L2-normalize (which==0: * 1/8 for Q; which==1: K; which==2: V no norm).
// Block: 128 threads (4 warps), tile M=128, N=64, K-step=64 (12 iters).
// smem (dynamic): As[128][68] tf32, Bs[64][72] tf32.
// ---------------------------------------------------------------------------
#define PROJ_SMEM ((128 * 68 + 64 * 72) * 4)

__global__ __launch_bounds__(128, 1) void proj_kernel(
    const float* __restrict__ Xq, const float* __restrict__ Wq, const float* __restrict__ bq,
    const float* __restrict__ Xk, const float* __restrict__ Wk, const float* __restrict__ bk,
    const float* __restrict__ Xv, const float* __restrict__ Wv, const float* __restrict__ bv)
{
    extern __shared__ uint32_t smem[];
    uint32_t* As = smem;            // [128][68]
    uint32_t* Bs = smem + 128 * 68; // [64][72]

    const int which = blockIdx.y;
    const float* X    = which == 0 ? Xq : which == 1 ? Xk : Xv;
    const float* W    = which == 0 ? Wq : which == 1 ? Wk : Wv;
    const float* bias = which == 0 ? bq : which == 1 ? bk : bv;
    float* out        = which == 0 ? g_Q : which == 1 ? g_K : g_V;
    const float post  = (which == 0) ? 0.125f : 1.0f;
    const bool do_norm = (which != 2);

    const int tid  = threadIdx.x;
    const int lane = tid & 31;
    const int warp = tid >> 5;
    const int g = lane >> 2, t = lane & 3;
    const int row0 = blockIdx.x * 128;
    const int wrow = warp * 32;

    float acc[2][8][4];
#pragma unroll
    for (int mf = 0; mf < 2; mf++)
#pragma unroll
        for (int nf = 0; nf < 8; nf++)
#pragma unroll
            for (int i = 0; i < 4; i++) acc[mf][nf][i] = 0.f;

    for (int kt = 0; kt < 12; kt++) {
        // stage A tile [128][64] -> tf32
#pragma unroll
        for (int i = 0; i < 16; i++) {
            int idx = tid + i * 128;
            int r = idx >> 4, c4 = idx & 15;
            float4 v = *(const float4*)(X + (size_t)(row0 + r) * 768 + kt * 64 + c4 * 4);
            uint32_t* dst = &As[r * 68 + c4 * 4];
            dst[0] = f2tf(v.x); dst[1] = f2tf(v.y); dst[2] = f2tf(v.z); dst[3] = f2tf(v.w);
        }
        // stage B tile [64][64] -> tf32
#pragma unroll
        for (int i = 0; i < 8; i++) {
            int idx = tid + i * 128;
            int r = idx >> 4, c4 = idx & 15;
            float4 v = *(const float4*)(W + (size_t)(kt * 64 + r) * 64 + c4 * 4);
            uint32_t* dst = &Bs[r * 72 + c4 * 4];
            dst[0] = f2tf(v.x); dst[1] = f2tf(v.y); dst[2] = f2tf(v.z); dst[3] = f2tf(v.w);
        }
        __syncthreads();
#pragma unroll
        for (int k8 = 0; k8 < 8; k8++) {
            uint32_t bfr[8][2];
#pragma unroll
            for (int nf = 0; nf < 8; nf++) {
                bfr[nf][0] = Bs[(k8 * 8 + t) * 72 + nf * 8 + g];
                bfr[nf][1] = Bs[(k8 * 8 + t + 4) * 72 + nf * 8 + g];
            }
#pragma unroll
            for (int mf = 0; mf < 2; mf++) {
                uint32_t a[4];
                int rb = (wrow + mf * 16 + g) * 68 + k8 * 8 + t;
                a[0] = As[rb];
                a[1] = As[rb + 8 * 68];
                a[2] = As[rb + 4];
                a[3] = As[rb + 8 * 68 + 4];
#pragma unroll
                for (int nf = 0; nf < 8; nf++) mma_tf32(acc[mf][nf], a, bfr[nf], acc[mf][nf]);
            }
        }
        __syncthreads();
    }

    // epilogue: bias, optional L2 row-normalize, store
#pragma unroll
    for (int mf = 0; mf < 2; mf++) {
#pragma unroll
        for (int nf = 0; nf < 8; nf++) {
            float b0 = bias[nf * 8 + t * 2];
            float b1 = bias[nf * 8 + t * 2 + 1];
            acc[mf][nf][0] += b0; acc[mf][nf][1] += b1;
            acc[mf][nf][2] += b0; acc[mf][nf][3] += b1;
        }
        float s0 = 1.f, s1 = 1.f;
        if (do_norm) {
            float q0 = 0.f, q1 = 0.f;
#pragma unroll
            for (int nf = 0; nf < 8; nf++) {
                q0 += acc[mf][nf][0] * acc[mf][nf][0] + acc[mf][nf][1] * acc[mf][nf][1];
                q1 += acc[mf][nf][2] * acc[mf][nf][2] + acc[mf][nf][3] * acc[mf][nf][3];
            }
            q0 += __shfl_xor_sync(0xffffffffu, q0, 1);
            q0 += __shfl_xor_sync(0xffffffffu, q0, 2);
            q1 += __shfl_xor_sync(0xffffffffu, q1, 1);
            q1 += __shfl_xor_sync(0xffffffffu, q1, 2);
            s0 = rsqrtf(q0) * post;
            s1 = rsqrtf(q1) * post;
        }
        int ra = row0 + wrow + mf * 16 + g;
#pragma unroll
        for (int nf = 0; nf < 8; nf++) {
            float2 v0 = make_float2(acc[mf][nf][0] * s0, acc[mf][nf][1] * s0);
            float2 v1 = make_float2(acc[mf][nf][2] * s1, acc[mf][nf][3] * s1);
            *(float2*)(out + (size_t)ra * 64 + nf * 8 + t * 2) = v0;
            *(float2*)(out + (size_t)(ra + 8) * 64 + nf * 8 + t * 2) = v1;
        }
    }
}

// ---------------------------------------------------------------------------
// Flash attention: per block (batch b, 128 q-rows). 4 warps, each warp owns 32
// q rows across full N=64. Online softmax; P staged through warp-private smem.
// smem: Qs[128][68], Ks[64][68], Vs[64][72], Ps[128][68] (all tf32 u32).
// ---------------------------------------------------------------------------
#define ATTN_SMEM ((128 * 68 + 64 * 68 + 64 * 72 + 128 * 68) * 4)

__global__ __launch_bounds__(128, 1) void attn_kernel(float* __restrict__ out)
{
    extern __shared__ uint32_t smem[];
    uint32_t* Qs = smem;                              // [128][68]
    uint32_t* Ks = Qs + 128 * 68;                     // [64][68]
    uint32_t* Vs = Ks + 64 * 68;                      // [64][72]
    uint32_t* Ps = Vs + 64 * 72;                      // [128][68]

    const int tid  = threadIdx.x;
    const int lane = tid & 31;
    const int warp = tid >> 5;
    const int g = lane >> 2, t = lane & 3;
    const int b = blockIdx.y, qt = blockIdx.x;
    const int base_q = b * 2048 + qt * 128;
    const int wrow = warp * 32;

    // load Q tile once
#pragma unroll
    for (int i = 0; i < 16; i++) {
        int idx = tid + i * 128;
        int r = idx >> 4, c4 = idx & 15;
        float4 v = *(const float4*)(g_Q + (size_t)(base_q + r) * 64 + c4 * 4);
        uint32_t* dst = &Qs[r * 68 + c4 * 4];
        dst[0] = f2tf(v.x); dst[1] = f2tf(v.y); dst[2] = f2tf(v.z); dst[3] = f2tf(v.w);
    }

    float o[2][8][4];
#pragma unroll
    for (int mf = 0; mf < 2; mf++)
#pragma unroll
        for (int nf = 0; nf < 8; nf++)
#pragma unroll
            for (int i = 0; i < 4; i++) o[mf][nf][i] = 0.f;
    float m[2][2] = {{-1e30f, -1e30f}, {-1e30f, -1e30f}};
    float l[2][2] = {{0.f, 0.f}, {0.f, 0.f}};

    for (int j = 0; j < 32; j++) {
        const int base_k = b * 2048 + j * 64;
        __syncthreads();  // prior K/V consumers done
#pragma unroll
        for (int i = 0; i < 8; i++) {
            int idx = tid + i * 128;
            int r = idx >> 4, c4 = idx & 15;
            float4 kv = *(const float4*)(g_K + (size_t)(base_k + r) * 64 + c4 * 4);
            uint32_t* dk = &Ks[r * 68 + c4 * 4];
            dk[0] = f2tf(kv.x); dk[1] = f2tf(kv.y); dk[2] = f2tf(kv.z); dk[3] = f2tf(kv.w);
            float4 vv = *(const float4*)(g_V + (size_t)(base_k + r) * 64 + c4 * 4);
            uint32_t* dv = &Vs[r * 72 + c4 * 4];
            dv[0] = f2tf(vv.x); dv[1] = f2tf(vv.y); dv[2] = f2tf(vv.z); dv[3] = f2tf(vv.w);
        }
        __syncthreads();

        // S = Qn @ Kn^T   (logits already scaled by folded 1/8)
        float s[2][8][4];
#pragma unroll
        for (int mf = 0; mf < 2; mf++)
#pragma unroll
            for (int nf = 0; nf < 8; nf++)
#pragma unroll
                for (int i = 0; i < 4; i++) s[mf][nf][i] = 0.f;
#pragma unroll
        for (int k8 = 0; k8 < 8; k8++) {
            uint32_t bfr[8][2];
#pragma unroll
            for (int nf = 0; nf < 8; nf++) {
                bfr[nf][0] = Ks[(nf * 8 + g) * 68 + k8 * 8 + t];
                bfr[nf][1] = Ks[(nf * 8 + g) * 68 + k8 * 8 + t + 4];
            }
#pragma unroll
            for (int mf = 0; mf < 2; mf++) {
                uint32_t a[4];
                int rb = (wrow + mf * 16 + g) * 68 + k8 * 8 + t;
                a[0] = Qs[rb];
                a[1] = Qs[rb + 8 * 68];
                a[2] = Qs[rb + 4];
                a[3] = Qs[rb + 8 * 68 + 4];
#pragma unroll
                for (int nf = 0; nf < 8; nf++) mma_tf32(s[mf][nf], a, bfr[nf], s[mf][nf]);
            }
        }

        // online softmax update + stage P to smem (warp-private rows)
#pragma unroll
        for (int mf = 0; mf < 2; mf++) {
            float vm0 = -1e30f, vm1 = -1e30f;
#pragma unroll
            for (int nf = 0; nf < 8; nf++) {
                vm0 = fmaxf(vm0, fmaxf(s[mf][nf][0], s[mf][nf][1]));
                vm1 = fmaxf(vm1, fmaxf(s[mf][nf][2], s[mf][nf][3]));
            }
            vm0 = fmaxf(vm0, __shfl_xor_sync(0xffffffffu, vm0, 1));
            vm0 = fmaxf(vm0, __shfl_xor_sync(0xffffffffu, vm0, 2));
            vm1 = fmaxf(vm1, __shfl_xor_sync(0xffffffffu, vm1, 1));
            vm1 = fmaxf(vm1, __shfl_xor_sync(0xffffffffu, vm1, 2));
            float mn0 = fmaxf(m[mf][0], vm0);
            float mn1 = fmaxf(m[mf][1], vm1);
            float alpha0 = exp2f((m[mf][0] - mn0) * LOG2E);
            float alpha1 = exp2f((m[mf][1] - mn1) * LOG2E);
            float rs0 = 0.f, rs1 = 0.f;
            int prow = (wrow + mf * 16 + g) * 68;
#pragma unroll
            for (int nf = 0; nf < 8; nf++) {
                float p0 = exp2f((s[mf][nf][0] - mn0) * LOG2E);
                float p1 = exp2f((s[mf][nf][1] - mn0) * LOG2E);
                float p2 = exp2f((s[mf][nf][2] - mn1) * LOG2E);
                float p3 = exp2f((s[mf][nf][3] - mn1) * LOG2E);
                rs0 += p0 + p1;
                rs1 += p2 + p3;
                Ps[prow + nf * 8 + t * 2]              = f2tf(p0);
                Ps[prow + nf * 8 + t * 2 + 1]          = f2tf(p1);
                Ps[prow + 8 * 68 + nf * 8 + t * 2]     = f2tf(p2);
                Ps[prow + 8 * 68 + nf * 8 + t * 2 + 1] = f2tf(p3);
            }
            rs0 += __shfl_xor_sync(0xffffffffu, rs0, 1);
            rs0 += __shfl_xor_sync(0xffffffffu, rs0, 2);
            rs1 += __shfl_xor_sync(0xffffffffu, rs1, 1);
            rs1 += __shfl_xor_sync(0xffffffffu, rs1, 2);
            l[mf][0] = l[mf][0] * alpha0 + rs0;
            l[mf][1] = l[mf][1] * alpha1 + rs1;
            m[mf][0] = mn0;
            m[mf][1] = mn1;
#pragma unroll
            for (int nf = 0; nf < 8; nf++) {
                o[mf][nf][0] *= alpha0; o[mf][nf][1] *= alpha0;
                o[mf][nf][2] *= alpha1; o[mf][nf][3] *= alpha1;
            }
        }
        __syncwarp();

        // O += P @ V
#pragma unroll
        for (int k8 = 0; k8 < 8; k8++) {
            uint32_t bfr[8][2];
#pragma unroll
            for (int nf = 0; nf < 8; nf++) {
                bfr[nf][0] = Vs[(k8 * 8 + t) * 72 + nf * 8 + g];
                bfr[nf][1] = Vs[(k8 * 8 + t + 4) * 72 + nf * 8 + g];
            }
#pragma unroll
            for (int mf = 0; mf < 2; mf++) {
                uint32_t a[4];
                int rb = (wrow + mf * 16 + g) * 68 + k8 * 8 + t;
                a[0] = Ps[rb];
                a[1] = Ps[rb + 8 * 68];
                a[2] = Ps[rb + 4];
                a[3] = Ps[rb + 8 * 68 + 4];
#pragma unroll
                for (int nf = 0; nf < 8; nf++) mma_tf32(o[mf][nf], a, bfr[nf], o[mf][nf]);
            }
        }
        __syncwarp();
    }

    // epilogue: divide by l and store
#pragma unroll
    for (int mf = 0; mf < 2; mf++) {
        float inv0 = 1.f / l[mf][0];
        float inv1 = 1.f / l[mf][1];
        int ra = base_q + wrow + mf * 16 + g;
#pragma unroll
        for (int nf = 0; nf < 8; nf++) {
            float2 v0 = make_float2(o[mf][nf][0] * inv0, o[mf][nf][1] * inv0);
            float2 v1 = make_float2(o[mf][nf][2] * inv1, o[mf][nf][3] * inv1);
            *(float2*)(out + (size_t)ra * 64 + nf * 8 + t * 2) = v0;
            *(float2*)(out + (size_t)(ra + 8) * 64 + nf * 8 + t * 2) = v1;
        }
    }
}

extern "C" void kernel_launch(void* const* d_in, const int* in_sizes, int n_in,
                              void* d_out, int out_size)
{
    const float* query = (const float*)d_in[0];
    const float* key   = (const float*)d_in[1];
    const float* value = (const float*)d_in[2];
    const float* Wq    = (const float*)d_in[3];
    const float* bq    = (const float*)d_in[4];
    const float* Wk    = (const float*)d_in[5];
    const float* bk    = (const float*)d_in[6];
    const float* Wv    = (const float*)d_in[7];
    const float* bv    = (const float*)d_in[8];

    cudaFuncSetAttribute(proj_kernel, cudaFuncAttributeMaxDynamicSharedMemorySize, PROJ_SMEM);
    cudaFuncSetAttribute(attn_kernel, cudaFuncAttributeMaxDynamicSharedMemorySize, ATTN_SMEM);

    proj_kernel<<<dim3(128, 3), 128, PROJ_SMEM>>>(query, Wq, bq, key, Wk, bk, value, Wv, bv);
    attn_kernel<<<dim3(16, 8), 128, ATTN_SMEM>>>((float*)d_out);
}

// round 2
// speedup vs baseline: 1.1235x; 1.1235x over previous
#include <cuda_runtime.h>
#include <cstdint>

#define LOG2E 1.4426950408889634f

// Scratch: projected Q (normalized, /8 folded), K (normalized), V — all stored
// pre-rounded to tf32 (RNA) so the attention kernel can consume raw bits.
__device__ float g_Q[8 * 2048 * 64];
__device__ float g_K[8 * 2048 * 64];
__device__ float g_V[8 * 2048 * 64];
// KV-split partial results
__device__ float g_Op[2][8 * 2048 * 64];
__device__ float g_Mp[2][8 * 2048];
__device__ float g_Lp[2][8 * 2048];

__device__ __forceinline__ uint32_t f2tf(float x) {
    uint32_t y;
    asm("cvt.rna.tf32.f32 %0, %1;" : "=r"(y) : "f"(x));
    return y;
}

__device__ __forceinline__ void cp16(uint32_t dst_smem, const void* src) {
    asm volatile("cp.async.ca.shared.global [%0], [%1], 16;"
                 :: "r"(dst_smem), "l"(src));
}

__device__ __forceinline__ void mma_tf32(float d[4], const uint32_t a[4],
                                         const uint32_t b[2], const float c[4]) {
    asm volatile(
        "mma.sync.aligned.m16n8k8.row.col.f32.tf32.tf32.f32 "
        "{%0,%1,%2,%3}, {%4,%5,%6,%7}, {%8,%9}, {%10,%11,%12,%13};"
        : "=f"(d[0]), "=f"(d[1]), "=f"(d[2]), "=f"(d[3])
        : "r"(a[0]), "r"(a[1]), "r"(a[2]), "r"(a[3]),
          "r"(b[0]), "r"(b[1]),
          "f"(c[0]), "f"(c[1]), "f"(c[2]), "f"(c[3]));
}

// ---------------------------------------------------------------------------
// Projection: out[16384,64] = X[16384,768] @ W[768,64] + bias, optional row
// L2-normalize. Outputs stored tf32-rounded.
// ---------------------------------------------------------------------------
#define PROJ_SMEM ((128 * 68 + 64 * 72) * 4)

__global__ __launch_bounds__(128, 3) void proj_kernel(
    const float* __restrict__ Xq, const float* __restrict__ Wq, const float* __restrict__ bq,
    const float* __restrict__ Xk, const float* __restrict__ Wk, const float* __restrict__ bk,
    const float* __restrict__ Xv, const float* __restrict__ Wv, const float* __restrict__ bv)
{
    extern __shared__ uint32_t smem[];
    uint32_t* As = smem;            // [128][68]
    uint32_t* Bs = smem + 128 * 68; // [64][72]

    const int which = blockIdx.y;
    const float* X    = which == 0 ? Xq : which == 1 ? Xk : Xv;
    const float* W    = which == 0 ? Wq : which == 1 ? Wk : Wv;
    const float* bias = which == 0 ? bq : which == 1 ? bk : bv;
    float* out        = which == 0 ? g_Q : which == 1 ? g_K : g_V;
    const float post  = (which == 0) ? 0.125f : 1.0f;
    const bool do_norm = (which != 2);

    const int tid  = threadIdx.x;
    const int lane = tid & 31;
    const int warp = tid >> 5;
    const int g = lane >> 2, t = lane & 3;
    const int row0 = blockIdx.x * 128;
    const int wrow = warp * 32;

    float acc[2][8][4];
#pragma unroll
    for (int mf = 0; mf < 2; mf++)
#pragma unroll
        for (int nf = 0; nf < 8; nf++)
#pragma unroll
            for (int i = 0; i < 4; i++) acc[mf][nf][i] = 0.f;

    for (int kt = 0; kt < 12; kt++) {
#pragma unroll
        for (int i = 0; i < 16; i++) {
            int idx = tid + i * 128;
            int r = idx >> 4, c4 = idx & 15;
            float4 v = *(const float4*)(X + (size_t)(row0 + r) * 768 + kt * 64 + c4 * 4);
            uint32_t* dst = &As[r * 68 + c4 * 4];
            dst[0] = f2tf(v.x); dst[1] = f2tf(v.y); dst[2] = f2tf(v.z); dst[3] = f2tf(v.w);
        }
#pragma unroll
        for (int i = 0; i < 8; i++) {
            int idx = tid + i * 128;
            int r = idx >> 4, c4 = idx & 15;
            float4 v = *(const float4*)(W + (size_t)(kt * 64 + r) * 64 + c4 * 4);
            uint32_t* dst = &Bs[r * 72 + c4 * 4];
            dst[0] = f2tf(v.x); dst[1] = f2tf(v.y); dst[2] = f2tf(v.z); dst[3] = f2tf(v.w);
        }
        __syncthreads();
#pragma unroll
        for (int k8 = 0; k8 < 8; k8++) {
            uint32_t bfr[8][2];
#pragma unroll
            for (int nf = 0; nf < 8; nf++) {
                bfr[nf][0] = Bs[(k8 * 8 + t) * 72 + nf * 8 + g];
                bfr[nf][1] = Bs[(k8 * 8 + t + 4) * 72 + nf * 8 + g];
            }
#pragma unroll
            for (int mf = 0; mf < 2; mf++) {
                uint32_t a[4];
                int rb = (wrow + mf * 16 + g) * 68 + k8 * 8 + t;
                a[0] = As[rb];
                a[1] = As[rb + 8 * 68];
                a[2] = As[rb + 4];
                a[3] = As[rb + 8 * 68 + 4];
#pragma unroll
                for (int nf = 0; nf < 8; nf++) mma_tf32(acc[mf][nf], a, bfr[nf], acc[mf][nf]);
            }
        }
        __syncthreads();
    }

#pragma unroll
    for (int mf = 0; mf < 2; mf++) {
#pragma unroll
        for (int nf = 0; nf < 8; nf++) {
            float b0 = bias[nf * 8 + t * 2];
            float b1 = bias[nf * 8 + t * 2 + 1];
            acc[mf][nf][0] += b0; acc[mf][nf][1] += b1;
            acc[mf][nf][2] += b0; acc[mf][nf][3] += b1;
        }
        float s0 = 1.f, s1 = 1.f;
        if (do_norm) {
            float q0 = 0.f, q1 = 0.f;
#pragma unroll
            for (int nf = 0; nf < 8; nf++) {
                q0 += acc[mf][nf][0] * acc[mf][nf][0] + acc[mf][nf][1] * acc[mf][nf][1];
                q1 += acc[mf][nf][2] * acc[mf][nf][2] + acc[mf][nf][3] * acc[mf][nf][3];
            }
            q0 += __shfl_xor_sync(0xffffffffu, q0, 1);
            q0 += __shfl_xor_sync(0xffffffffu, q0, 2);
            q1 += __shfl_xor_sync(0xffffffffu, q1, 1);
            q1 += __shfl_xor_sync(0xffffffffu, q1, 2);
            s0 = rsqrtf(q0) * post;
            s1 = rsqrtf(q1) * post;
        }
        int ra = row0 + wrow + mf * 16 + g;
#pragma unroll
        for (int nf = 0; nf < 8; nf++) {
            // store tf32-rounded so attn can consume raw bits exactly
            float2 v0 = make_float2(__uint_as_float(f2tf(acc[mf][nf][0] * s0)),
                                    __uint_as_float(f2tf(acc[mf][nf][1] * s0)));
            float2 v1 = make_float2(__uint_as_float(f2tf(acc[mf][nf][2] * s1)),
                                    __uint_as_float(f2tf(acc[mf][nf][3] * s1)));
            *(float2*)(out + (size_t)ra * 64 + nf * 8 + t * 2) = v0;
            *(float2*)(out + (size_t)(ra + 8) * 64 + nf * 8 + t * 2) = v1;
        }
    }
}

// ---------------------------------------------------------------------------
// Flash attention, KV-split x2. Block = (batch b, 128 q-rows, split z).
// 4 warps x 32 q-rows. cp.async staging of pre-rounded tf32 Q/K/V.
// Writes unnormalized partial O plus per-row (m, l).
// ---------------------------------------------------------------------------
#define ATTN_SMEM ((128 * 68 + 64 * 68 + 64 * 72 + 128 * 68) * 4)

__global__ __launch_bounds__(128, 2) void attn_kernel()
{
    extern __shared__ uint32_t smem[];
    uint32_t* Qs = smem;                              // [128][68]
    uint32_t* Ks = Qs + 128 * 68;                     // [64][68]
    uint32_t* Vs = Ks + 64 * 68;                      // [64][72]
    uint32_t* Ps = Vs + 64 * 72;                      // [128][68]
    const uint32_t sb = (uint32_t)__cvta_generic_to_shared(smem);
    const uint32_t QsB = sb;
    const uint32_t KsB = sb + 128 * 68 * 4;
    const uint32_t VsB = KsB + 64 * 68 * 4;

    const int tid  = threadIdx.x;
    const int lane = tid & 31;
    const int warp = tid >> 5;
    const int g = lane >> 2, t = lane & 3;
    const int b = blockIdx.y, qt = blockIdx.x, split = blockIdx.z;
    const int base_q = b * 2048 + qt * 128;
    const int wrow = warp * 32;

    // async-load Q tile (raw tf32 bits)
    {
        const int r = tid >> 4, c4 = tid & 15;  // 16 chunks/thread below
#pragma unroll
        for (int i = 0; i < 16; i++) {
            int idx = tid + i * 128;
            int rr = idx >> 4, cc = idx & 15;
            cp16(QsB + (rr * 68 + cc * 4) * 4,
                 g_Q + (size_t)(base_q + rr) * 64 + cc * 4);
        }
        (void)r; (void)c4;
    }

    float o[2][8][4];
#pragma unroll
    for (int mf = 0; mf < 2; mf++)
#pragma unroll
        for (int nf = 0; nf < 8; nf++)
#pragma unroll
            for (int i = 0; i < 4; i++) o[mf][nf][i] = 0.f;
    float m[2][2] = {{-1e30f, -1e30f}, {-1e30f, -1e30f}};
    float l[2][2] = {{0.f, 0.f}, {0.f, 0.f}};

    const int j0 = split * 16;
    for (int j = j0; j < j0 + 16; j++) {
        const int base_k = b * 2048 + j * 64;
        __syncthreads();  // prior K/V consumers done
#pragma unroll
        for (int i = 0; i < 8; i++) {
            int idx = tid + i * 128;
            int r = idx >> 4, c4 = idx & 15;
            cp16(KsB + (r * 68 + c4 * 4) * 4, g_K + (size_t)(base_k + r) * 64 + c4 * 4);
            cp16(VsB + (r * 72 + c4 * 4) * 4, g_V + (size_t)(base_k + r) * 64 + c4 * 4);
        }
        asm volatile("cp.async.commit_group;");
        asm volatile("cp.async.wait_group 0;");
        __syncthreads();

        // S = Qn @ Kn^T
        float s[2][8][4];
#pragma unroll
        for (int mf = 0; mf < 2; mf++)
#pragma unroll
            for (int nf = 0; nf < 8; nf++)
#pragma unroll
                for (int i = 0; i < 4; i++) s[mf][nf][i] = 0.f;
#pragma unroll
        for (int k8 = 0; k8 < 8; k8++) {
            uint32_t bfr[8][2];
#pragma unroll
            for (int nf = 0; nf < 8; nf++) {
                bfr[nf][0] = Ks[(nf * 8 + g) * 68 + k8 * 8 + t];
                bfr[nf][1] = Ks[(nf * 8 + g) * 68 + k8 * 8 + t + 4];
            }
#pragma unroll
            for (int mf = 0; mf < 2; mf++) {
                uint32_t a[4];
                int rb = (wrow + mf * 16 + g) * 68 + k8 * 8 + t;
                a[0] = Qs[rb];
                a[1] = Qs[rb + 8 * 68];
                a[2] = Qs[rb + 4];
                a[3] = Qs[rb + 8 * 68 + 4];
#pragma unroll
                for (int nf = 0; nf < 8; nf++) mma_tf32(s[mf][nf], a, bfr[nf], s[mf][nf]);
            }
        }

        // online softmax + stage P (tf32 RNA) to warp-private smem rows
#pragma unroll
        for (int mf = 0; mf < 2; mf++) {
            float vm0 = -1e30f, vm1 = -1e30f;
#pragma unroll
            for (int nf = 0; nf < 8; nf++) {
                vm0 = fmaxf(vm0, fmaxf(s[mf][nf][0], s[mf][nf][1]));
                vm1 = fmaxf(vm1, fmaxf(s[mf][nf][2], s[mf][nf][3]));
            }
            vm0 = fmaxf(vm0, __shfl_xor_sync(0xffffffffu, vm0, 1));
            vm0 = fmaxf(vm0, __shfl_xor_sync(0xffffffffu, vm0, 2));
            vm1 = fmaxf(vm1, __shfl_xor_sync(0xffffffffu, vm1, 1));
            vm1 = fmaxf(vm1, __shfl_xor_sync(0xffffffffu, vm1, 2));
            float mn0 = fmaxf(m[mf][0], vm0);
            float mn1 = fmaxf(m[mf][1], vm1);
            float alpha0 = exp2f((m[mf][0] - mn0) * LOG2E);
            float alpha1 = exp2f((m[mf][1] - mn1) * LOG2E);
            float rs0 = 0.f, rs1 = 0.f;
            int prow = (wrow + mf * 16 + g) * 68;
#pragma unroll
            for (int nf = 0; nf < 8; nf++) {
                float p0 = exp2f((s[mf][nf][0] - mn0) * LOG2E);
                float p1 = exp2f((s[mf][nf][1] - mn0) * LOG2E);
                float p2 = exp2f((s[mf][nf][2] - mn1) * LOG2E);
                float p3 = exp2f((s[mf][nf][3] - mn1) * LOG2E);
                rs0 += p0 + p1;
                rs1 += p2 + p3;
                Ps[prow + nf * 8 + t * 2]              = f2tf(p0);
                Ps[prow + nf * 8 + t * 2 + 1]          = f2tf(p1);
                Ps[prow + 8 * 68 + nf * 8 + t * 2]     = f2tf(p2);
                Ps[prow + 8 * 68 + nf * 8 + t * 2 + 1] = f2tf(p3);
            }
            rs0 += __shfl_xor_sync(0xffffffffu, rs0, 1);
            rs0 += __shfl_xor_sync(0xffffffffu, rs0, 2);
            rs1 += __shfl_xor_sync(0xffffffffu, rs1, 1);
            rs1 += __shfl_xor_sync(0xffffffffu, rs1, 2);
            l[mf][0] = l[mf][0] * alpha0 + rs0;
            l[mf][1] = l[mf][1] * alpha1 + rs1;
            m[mf][0] = mn0;
            m[mf][1] = mn1;
#pragma unroll
            for (int nf = 0; nf < 8; nf++) {
                o[mf][nf][0] *= alpha0; o[mf][nf][1] *= alpha0;
                o[mf][nf][2] *= alpha1; o[mf][nf][3] *= alpha1;
            }
        }
        __syncwarp();

        // O += P @ V
#pragma unroll
        for (int k8 = 0; k8 < 8; k8++) {
            uint32_t bfr[8][2];
#pragma unroll
            for (int nf = 0; nf < 8; nf++) {
                bfr[nf][0] = Vs[(k8 * 8 + t) * 72 + nf * 8 + g];
                bfr[nf][1] = Vs[(k8 * 8 + t + 4) * 72 + nf * 8 + g];
            }
#pragma unroll
            for (int mf = 0; mf < 2; mf++) {
                uint32_t a[4];
                int rb = (wrow + mf * 16 + g) * 68 + k8 * 8 + t;
                a[0] = Ps[rb];
                a[1] = Ps[rb + 8 * 68];
                a[2] = Ps[rb + 4];
                a[3] = Ps[rb + 8 * 68 + 4];
#pragma unroll
                for (int nf = 0; nf < 8; nf++) mma_tf32(o[mf][nf], a, bfr[nf], o[mf][nf]);
            }
        }
        __syncwarp();
    }

    // epilogue: store unnormalized partial O and per-row m, l
    float* Op = g_Op[split];
    float* Mp = g_Mp[split];
    float* Lp = g_Lp[split];
#pragma unroll
    for (int mf = 0; mf < 2; mf++) {
        int ra = base_q + wrow + mf * 16 + g;
        if (t == 0) {
            Mp[ra]     = m[mf][0];
            Lp[ra]     = l[mf][0];
            Mp[ra + 8] = m[mf][1];
            Lp[ra + 8] = l[mf][1];
        }
#pragma unroll
        for (int nf = 0; nf < 8; nf++) {
            float2 v0 = make_float2(o[mf][nf][0], o[mf][nf][1]);
            float2 v1 = make_float2(o[mf][nf][2], o[mf][nf][3]);
            *(float2*)(Op + (size_t)ra * 64 + nf * 8 + t * 2) = v0;
            *(float2*)(Op + (size_t)(ra + 8) * 64 + nf * 8 + t * 2) = v1;
        }
    }
}

// ---------------------------------------------------------------------------
// Combine the two KV-split partials: out = (o1*a1 + o2*a2) / (l1*a1 + l2*a2)
// ---------------------------------------------------------------------------
__global__ __launch_bounds__(256) void combine_kernel(float* __restrict__ out)
{
    int vid = blockIdx.x * 256 + threadIdx.x;   // 262144 float4s
    int row = vid >> 4;
    int c4  = vid & 15;
    float m1 = g_Mp[0][row], m2 = g_Mp[1][row];
    float l1 = g_Lp[0][row], l2 = g_Lp[1][row];
    float mm = fmaxf(m1, m2);
    float a1 = exp2f((m1 - mm) * LOG2E);
    float a2 = exp2f((m2 - mm) * LOG2E);
    float inv = 1.f / (l1 * a1 + l2 * a2);
    const float4 o1 = *(const float4*)(&g_Op[0][(size_t)row * 64 + c4 * 4]);
    const float4 o2 = *(const float4*)(&g_Op[1][(size_t)row * 64 + c4 * 4]);
    float4 r;
    r.x = (o1.x * a1 + o2.x * a2) * inv;
    r.y = (o1.y * a1 + o2.y * a2) * inv;
    r.z = (o1.z * a1 + o2.z * a2) * inv;
    r.w = (o1.w * a1 + o2.w * a2) * inv;
    *(float4*)(out + (size_t)vid * 4) = r;
}

extern "C" void kernel_launch(void* const* d_in, const int* in_sizes, int n_in,
                              void* d_out, int out_size)
{
    const float* query = (const float*)d_in[0];
    const float* key   = (const float*)d_in[1];
    const float* value = (const float*)d_in[2];
    const float* Wq    = (const float*)d_in[3];
    const float* bq    = (const float*)d_in[4];
    const float* Wk    = (const float*)d_in[5];
    const float* bk    = (const float*)d_in[6];
    const float* Wv    = (const float*)d_in[7];
    const float* bv    = (const float*)d_in[8];

    cudaFuncSetAttribute(proj_kernel, cudaFuncAttributeMaxDynamicSharedMemorySize, PROJ_SMEM);
    cudaFuncSetAttribute(attn_kernel, cudaFuncAttributeMaxDynamicSharedMemorySize, ATTN_SMEM);

    proj_kernel<<<dim3(128, 3), 128, PROJ_SMEM>>>(query, Wq, bq, key, Wk, bk, value, Wv, bv);
    attn_kernel<<<dim3(16, 8, 2), 128, ATTN_SMEM>>>();
    combine_kernel<<<1024, 256>>>((float*)d_out);
}